// round 15
// baseline (speedup 1.0000x reference)
#include <cuda_runtime.h>
#include <cuda_bf16.h>
#include <cuda_fp16.h>
#include <math.h>
#include <stdint.h>

#define B_  16
#define C_  128
#define O_  256
#define H_  96
#define W_  96
#define KH  5
#define HO  92
#define WO  92
#define HW_IN  (H_*W_)        // 9216
#define HW_OUT (HO*WO)        // 8464
#define KK  25
#define NPT 67                // ceil(8464/128)
#define NSTAGE 50             // 25 taps * 2 k64-chunks

// ---------------- device scratch (no allocation allowed) ----------------
// 16-bit planes: path0 = fp16 mu, path1 = bf16 sigma  [path][b][pix][c]
__device__ __align__(128) unsigned short g_Ah[(size_t)2*B_*HW_IN*128];
// Weights: [path][og][tap][o_local(128)][c(128)]: path0 = fp16 W, path1 = bf16 W^2
__device__ __align__(128) unsigned short g_Wp[(size_t)2*2*KK*16384];
__device__ float g_Tp[2*B_*HW_IN];   // [path][b][pix]: path0 = sum mu^2, path1 = sum sigma
__device__ float g_S [B_*HW_OUT];
__device__ float g_sp[O_];

// ---------------- PTX helpers ----------------
__device__ __forceinline__ uint32_t smem_u32(const void* p){
    return (uint32_t)__cvta_generic_to_shared((void*)p);
}
__device__ __forceinline__ void cp16(uint32_t dst, const void* src){
    asm volatile("cp.async.cg.shared.global [%0], [%1], 16;\n" :: "r"(dst), "l"(src));
}
__device__ __forceinline__ void cp_commit(){ asm volatile("cp.async.commit_group;\n" ::: "memory"); }
template<int N> __device__ __forceinline__ void cp_wait(){
    asm volatile("cp.async.wait_group %0;\n" :: "n"(N) : "memory");
}
__device__ __forceinline__ void ldsm4(uint32_t* r, uint32_t addr){
    asm volatile("ldmatrix.sync.aligned.m8n8.x4.shared.b16 {%0,%1,%2,%3}, [%4];"
        : "=r"(r[0]), "=r"(r[1]), "=r"(r[2]), "=r"(r[3]) : "r"(addr));
}
// bf16 MMA (sigma path)
#define MMAB(acc, a, b0, b1)                                                       \
    asm volatile("mma.sync.aligned.m16n8k16.row.col.f32.bf16.bf16.f32 "            \
                 "{%0,%1,%2,%3},{%4,%5,%6,%7},{%8,%9},{%0,%1,%2,%3};"              \
                 : "+f"((acc)[0]), "+f"((acc)[1]), "+f"((acc)[2]), "+f"((acc)[3])  \
                 : "r"((a)[0]), "r"((a)[1]), "r"((a)[2]), "r"((a)[3]),             \
                   "r"(b0), "r"(b1))
// fp16 MMA (mu path)
#define MMAH(acc, a, b0, b1)                                                       \
    asm volatile("mma.sync.aligned.m16n8k16.row.col.f32.f16.f16.f32 "              \
                 "{%0,%1,%2,%3},{%4,%5,%6,%7},{%8,%9},{%0,%1,%2,%3};"              \
                 : "+f"((acc)[0]), "+f"((acc)[1]), "+f"((acc)[2]), "+f"((acc)[3])  \
                 : "r"((a)[0]), "r"((a)[1]), "r"((a)[2]), "r"((a)[3]),             \
                   "r"(b0), "r"(b1))

// ---------------- prep kernels ----------------
__global__ void transpose_split_kernel(const float* __restrict__ mu,
                                       const float* __restrict__ sg) {
    __shared__ float ts[C_][65];
    int pt = blockIdx.x, b = blockIdx.y, path = blockIdx.z;
    const float* src = (path ? sg : mu) + (size_t)b * C_ * HW_IN + pt * 64;
    int tid = threadIdx.x;
    for (int i = tid; i < C_ * 64; i += 256) {
        int c = i >> 6, pi = i & 63;
        ts[c][pi] = src[(size_t)c * HW_IN + pi];
    }
    __syncthreads();
    size_t obase = (size_t)(path * B_ + b) * HW_IN * 128;
    int p0 = pt * 64;
    for (int i = tid; i < 64 * C_; i += 256) {
        int pi = i >> 7, c = i & 127;
        float v = ts[c][pi];
        size_t idx = obase + (size_t)(p0 + pi) * 128 + c;
        g_Ah[idx] = path == 0 ? __half_as_ushort(__float2half(v))
                              : __bfloat16_as_ushort(__float2bfloat16(v));
    }
    // fused channel sum: path0 -> sum mu^2, path1 -> sum sigma
    if (tid < 64) {
        float acc = 0.0f;
        #pragma unroll 8
        for (int c = 0; c < C_; ++c) {
            float v = ts[c][tid];
            acc += path ? v : v * v;
        }
        g_Tp[(size_t)(path * B_ + b) * HW_IN + p0 + tid] = acc;
    }
}

__global__ void wprep_kernel(const float* __restrict__ W,
                             const float* __restrict__ w_sigma) {
    int gid = blockIdx.x * blockDim.x + threadIdx.x;
    if (gid < O_) {
        float w = fmaxf(w_sigma[gid], -88.0f);
        g_sp[gid] = log1pf(expf(w));
    }
    if (gid >= O_ * C_) return;
    int o = gid >> 7, c = gid & 127;
    int og = o >> 7, ol = o & 127;
    const float* wp = W + ((size_t)o * C_ + c) * KK;
    int dst_in = ol * 128 + c;
    #pragma unroll
    for (int tap = 0; tap < KK; ++tap) {
        float w  = wp[tap];
        size_t blk0 = (size_t)((0 * 2 + og) * KK + tap);
        size_t blk1 = (size_t)((1 * 2 + og) * KK + tap);
        g_Wp[blk0 * 16384 + dst_in] = __half_as_ushort(__float2half(w));
        g_Wp[blk1 * 16384 + dst_in] = __bfloat16_as_ushort(__float2bfloat16(w * w));
    }
}

__global__ void boxsum_kernel() {
    int i = blockIdx.x * blockDim.x + threadIdx.x;
    if (i >= B_*HW_OUT) return;
    int b = i / HW_OUT;
    int p = i - b * HW_OUT;
    int y = p / WO;
    int x = p - y * WO;
    const float* t0 = g_Tp + (size_t)b * HW_IN;
    const float* t1 = g_Tp + (size_t)(B_ + b) * HW_IN;
    float acc = 0.0f;
    #pragma unroll
    for (int dy = 0; dy < KH; ++dy)
        #pragma unroll
        for (int dx = 0; dx < KH; ++dx) {
            int off = (y + dy) * W_ + (x + dx);
            acc += t0[off] + t1[off];
        }
    g_S[i] = acc;
}

// ---------------- main mma.sync conv: 4 warps, 64x64 warp tiles ----------------
// CTA = 128 threads, tile 128px x 128o. Warp grid 2x2, warp tile 64x64 -> smem
// fragment reads = tile*(nw_m+nw_n) = 4 units vs 6 before (-33% L1 traffic).
// Buffer (32KB): A 16K | B 16K. Ring of 3 = 96KB. k64 stages. Single-term paths.
// Row = one 128B line. SW128 swizzle: addr = row*128 + ((chunk ^ (row&7))<<4);
// k16-slice ks selects chunks via addr ^ (ks<<5).
#define BUFSZ   32768u
#define OFF_BH  16384u
#define SMEM_MAIN 98304   // >= epilogue 128*132*4 = 67584
#define NTHR 128

__global__ void __launch_bounds__(NTHR, 2)
mma_conv_kernel(const float* __restrict__ bias, float* __restrict__ out) {
    extern __shared__ char smem[];
    uint32_t sb = smem_u32(smem);
    int tid = threadIdx.x;
    int lane = tid & 31, wid = tid >> 5;
    int warp_m = wid >> 1, warp_n = wid & 1;

    int ptile = blockIdx.x, b = blockIdx.y;
    int path = blockIdx.z & 1, og = blockIdx.z >> 1;

    // ---- staging setup: each thread owns one full 128B row of A and of B ----
    int ar = tid;                            // row 0..127
    int aq = ar & 7;
    int pA  = ptile * 128 + ar;
    int pcA = min(pA, HW_OUT - 1);
    int py = pcA / WO, px = pcA - py * WO;
    const unsigned short* aplane = g_Ah + (size_t)(path * B_ + b) * HW_IN * 128;
    uint32_t a_sm_base = (uint32_t)ar * 128;

    const char* wblk = (const char*)g_Wp +
        (size_t)((path * 2 + og) * KK) * 32768;

    auto stage = [&](int s, int buf) {
        int tap = s >> 1, kc = s & 1;
        int ki = tap / 5, kj = tap - ki * 5;
        uint32_t base = sb + buf * BUFSZ;
        // A: full 128B (k64) row for this pixel
        const char* arow =
            (const char*)(aplane + ((size_t)((py + ki) * W_ + (px + kj))) * 128)
            + kc * 128;
        uint32_t adst = base + a_sm_base;
        #pragma unroll
        for (int j = 0; j < 8; ++j)
            cp16(adst + (uint32_t)((j ^ aq) << 4), arow + j * 16);
        // B: full 128B (k64) row for weight o_local = ar
        const char* bsrc = wblk + (size_t)tap * 32768 + (size_t)ar * 256 + kc * 128;
        uint32_t bdst = base + OFF_BH + a_sm_base;
        #pragma unroll
        for (int j = 0; j < 8; ++j)
            cp16(bdst + (uint32_t)((j ^ aq) << 4), bsrc + j * 16);
        cp_commit();
    };

    // ---- ldmatrix swizzled base offsets (slice ks XORs addr with ks<<5) ----
    int rA = warp_m * 64 + (lane & 15);
    int cA = lane >> 4;
    uint32_t offA[4];
    #pragma unroll
    for (int mi = 0; mi < 4; ++mi) {
        int row = rA + mi * 16;
        offA[mi] = (uint32_t)(row * 128 + ((cA ^ (row & 7)) << 4));
    }
    int rB = warp_n * 64 + ((lane >> 4) << 3) + (lane & 7);
    int cB = (lane >> 3) & 1;
    uint32_t offB[4];
    #pragma unroll
    for (int n2 = 0; n2 < 4; ++n2) {
        int row = rB + n2 * 16;
        offB[n2] = (uint32_t)(row * 128 + ((cB ^ (row & 7)) << 4));
    }

    float acc[4][8][4];
    #pragma unroll
    for (int mi = 0; mi < 4; ++mi)
        #pragma unroll
        for (int ni = 0; ni < 8; ++ni)
            #pragma unroll
            for (int j = 0; j < 4; ++j) acc[mi][ni][j] = 0.0f;

    stage(0, 0);
    stage(1, 1);

    for (int s = 0; s < NSTAGE; ++s) {
        int buf = s % 3;
        // 1) ensure stage(s) landed (stage s+1 stays in flight)
        if (s + 1 < NSTAGE) cp_wait<1>(); else cp_wait<0>();
        // 2) publish stage(s); confirms buffer (s+2)%3 == (s-1)%3 consumed
        __syncthreads();
        // 3) refill the freed buffer
        if (s + 2 < NSTAGE) stage(s + 2, (s + 2) % 3);

        uint32_t base = sb + buf * BUFSZ;

        #pragma unroll
        for (int ks = 0; ks < 4; ++ks) {
            uint32_t x = (uint32_t)ks << 5;
            uint32_t ah[4][4], bh[4][4];
            #pragma unroll
            for (int mi = 0; mi < 4; ++mi)
                ldsm4(ah[mi], base + (offA[mi] ^ x));
            #pragma unroll
            for (int n2 = 0; n2 < 4; ++n2)
                ldsm4(bh[n2], base + OFF_BH + (offB[n2] ^ x));

            if (path == 0) {
                #pragma unroll
                for (int mi = 0; mi < 4; ++mi)
                    #pragma unroll
                    for (int n2 = 0; n2 < 4; ++n2) {
                        MMAH(acc[mi][2*n2],   ah[mi], bh[n2][0], bh[n2][1]);
                        MMAH(acc[mi][2*n2+1], ah[mi], bh[n2][2], bh[n2][3]);
                    }
            } else {
                #pragma unroll
                for (int mi = 0; mi < 4; ++mi)
                    #pragma unroll
                    for (int n2 = 0; n2 < 4; ++n2) {
                        MMAB(acc[mi][2*n2],   ah[mi], bh[n2][0], bh[n2][1]);
                        MMAB(acc[mi][2*n2+1], ah[mi], bh[n2][2], bh[n2][3]);
                    }
            }
        }
    }
    __syncthreads();

    // ---- epilogue: transpose via SMEM, coalesced float4 stores ----
    float* eps = (float*)smem;                 // [n=128][m pitch 132]
    #pragma unroll
    for (int mi = 0; mi < 4; ++mi) {
        int m0 = warp_m * 64 + mi * 16 + (lane >> 2);
        #pragma unroll
        for (int ni = 0; ni < 8; ++ni) {
            int n0 = warp_n * 64 + ni * 8 + 2 * (lane & 3);
            eps[n0 * 132 + m0]           = acc[mi][ni][0];
            eps[(n0 + 1) * 132 + m0]     = acc[mi][ni][1];
            eps[n0 * 132 + m0 + 8]       = acc[mi][ni][2];
            eps[(n0 + 1) * 132 + m0 + 8] = acc[mi][ni][3];
        }
    }
    __syncthreads();

    int pix0 = ptile * 128;
    int m = lane * 4;
    bool ok = (pix0 + m) < HW_OUT;
    if (path == 0) {
        #pragma unroll 1
        for (int rr = 0; rr < 32; ++rr) {
            int r = rr * 4 + wid;
            int o = og * 128 + r;
            float4 v = *(float4*)&eps[r * 132 + m];
            float bz = bias[o];
            v.x += bz; v.y += bz; v.z += bz; v.w += bz;
            if (ok)
                *(float4*)&out[((size_t)(b * O_ + o)) * HW_OUT + pix0 + m] = v;
        }
    } else {
        float* out2 = out + (size_t)B_ * O_ * HW_OUT;
        float4 sv = make_float4(0.f, 0.f, 0.f, 0.f);
        if (ok) sv = *(float4*)&g_S[(size_t)b * HW_OUT + pix0 + m];
        #pragma unroll 1
        for (int rr = 0; rr < 32; ++rr) {
            int r = rr * 4 + wid;
            int o = og * 128 + r;
            float4 v = *(float4*)&eps[r * 132 + m];
            float sp = g_sp[o];
            v.x = (sp * sv.x + v.x) * 0.001f;
            v.y = (sp * sv.y + v.y) * 0.001f;
            v.z = (sp * sv.z + v.z) * 0.001f;
            v.w = (sp * sv.w + v.w) * 0.001f;
            if (ok)
                *(float4*)&out2[((size_t)(b * O_ + o)) * HW_OUT + pix0 + m] = v;
        }
    }
}

// ---------------------------------------------------------------------------
extern "C" void kernel_launch(void* const* d_in, const int* in_sizes, int n_in,
                              void* d_out, int out_size) {
    const float* mu_x    = (const float*)d_in[0];
    const float* sigma_x = (const float*)d_in[1];
    const float* W       = (const float*)d_in[2];
    const float* bias    = (const float*)d_in[3];
    const float* w_sigma = (const float*)d_in[4];
    float* out = (float*)d_out;

    cudaFuncSetAttribute(mma_conv_kernel,
                         cudaFuncAttributeMaxDynamicSharedMemorySize, SMEM_MAIN);

    {
        dim3 g(HW_IN / 64, B_, 2);                 // 144 x 16 x 2
        transpose_split_kernel<<<g, 256>>>(mu_x, sigma_x);
    }
    wprep_kernel<<<(O_ * C_ + 255) / 256, 256>>>(W, w_sigma);
    {
        int n = B_ * HW_OUT;
        boxsum_kernel<<<(n + 255) / 256, 256>>>();
    }
    {
        dim3 grid(NPT, B_, 4);                     // 67 x 16 x 4 = 4288 CTAs
        mma_conv_kernel<<<grid, NTHR, SMEM_MAIN>>>(bias, out);
    }
}

// round 16
// speedup vs baseline: 1.4906x; 1.4906x over previous
#include <cuda_runtime.h>
#include <cuda_bf16.h>
#include <cuda_fp16.h>
#include <math.h>
#include <stdint.h>

#define B_  16
#define C_  128
#define O_  256
#define H_  96
#define W_  96
#define KH  5
#define HO  92
#define WO  92
#define HW_IN  (H_*W_)        // 9216
#define HW_OUT (HO*WO)        // 8464
#define KK  25
#define NPT 67                // ceil(8464/128)
#define NSTAGE 50             // 25 taps * 2 k64-chunks

// ---------------- device scratch (no allocation allowed) ----------------
// 16-bit planes: path0 = fp16 mu, path1 = bf16 sigma  [path][b][pix][c]
__device__ __align__(128) unsigned short g_Ah[(size_t)2*B_*HW_IN*128];
// Weights: [path][og][tap][o_local(128)][c(128)]: path0 = fp16 W, path1 = bf16 W^2
__device__ __align__(128) unsigned short g_Wp[(size_t)2*2*KK*16384];
__device__ float g_Tp[2*B_*HW_IN];   // [path][b][pix]: path0 = sum mu^2, path1 = sum sigma
__device__ float g_S [B_*HW_OUT];
__device__ float g_sp[O_];

// ---------------- PTX helpers ----------------
__device__ __forceinline__ uint32_t smem_u32(const void* p){
    return (uint32_t)__cvta_generic_to_shared((void*)p);
}
__device__ __forceinline__ void cp16(uint32_t dst, const void* src){
    asm volatile("cp.async.cg.shared.global [%0], [%1], 16;\n" :: "r"(dst), "l"(src));
}
__device__ __forceinline__ void cp_commit(){ asm volatile("cp.async.commit_group;\n" ::: "memory"); }
template<int N> __device__ __forceinline__ void cp_wait(){
    asm volatile("cp.async.wait_group %0;\n" :: "n"(N) : "memory");
}
__device__ __forceinline__ void ldsm4(uint32_t* r, uint32_t addr){
    asm volatile("ldmatrix.sync.aligned.m8n8.x4.shared.b16 {%0,%1,%2,%3}, [%4];"
        : "=r"(r[0]), "=r"(r[1]), "=r"(r[2]), "=r"(r[3]) : "r"(addr));
}
// bf16 MMA (sigma path)
#define MMAB(acc, a, b0, b1)                                                       \
    asm volatile("mma.sync.aligned.m16n8k16.row.col.f32.bf16.bf16.f32 "            \
                 "{%0,%1,%2,%3},{%4,%5,%6,%7},{%8,%9},{%0,%1,%2,%3};"              \
                 : "+f"((acc)[0]), "+f"((acc)[1]), "+f"((acc)[2]), "+f"((acc)[3])  \
                 : "r"((a)[0]), "r"((a)[1]), "r"((a)[2]), "r"((a)[3]),             \
                   "r"(b0), "r"(b1))
// fp16 MMA (mu path)
#define MMAH(acc, a, b0, b1)                                                       \
    asm volatile("mma.sync.aligned.m16n8k16.row.col.f32.f16.f16.f32 "              \
                 "{%0,%1,%2,%3},{%4,%5,%6,%7},{%8,%9},{%0,%1,%2,%3};"              \
                 : "+f"((acc)[0]), "+f"((acc)[1]), "+f"((acc)[2]), "+f"((acc)[3])  \
                 : "r"((a)[0]), "r"((a)[1]), "r"((a)[2]), "r"((a)[3]),             \
                   "r"(b0), "r"(b1))

// ---------------- prep kernels ----------------
__global__ void transpose_split_kernel(const float* __restrict__ mu,
                                       const float* __restrict__ sg) {
    __shared__ float ts[C_][65];
    int pt = blockIdx.x, b = blockIdx.y, path = blockIdx.z;
    const float* src = (path ? sg : mu) + (size_t)b * C_ * HW_IN + pt * 64;
    int tid = threadIdx.x;
    for (int i = tid; i < C_ * 64; i += 256) {
        int c = i >> 6, pi = i & 63;
        ts[c][pi] = src[(size_t)c * HW_IN + pi];
    }
    __syncthreads();
    size_t obase = (size_t)(path * B_ + b) * HW_IN * 128;
    int p0 = pt * 64;
    for (int i = tid; i < 64 * C_; i += 256) {
        int pi = i >> 7, c = i & 127;
        float v = ts[c][pi];
        size_t idx = obase + (size_t)(p0 + pi) * 128 + c;
        g_Ah[idx] = path == 0 ? __half_as_ushort(__float2half(v))
                              : __bfloat16_as_ushort(__float2bfloat16(v));
    }
    // fused channel sum: path0 -> sum mu^2, path1 -> sum sigma
    if (tid < 64) {
        float acc = 0.0f;
        #pragma unroll 8
        for (int c = 0; c < C_; ++c) {
            float v = ts[c][tid];
            acc += path ? v : v * v;
        }
        g_Tp[(size_t)(path * B_ + b) * HW_IN + p0 + tid] = acc;
    }
}

__global__ void wprep_kernel(const float* __restrict__ W,
                             const float* __restrict__ w_sigma) {
    int gid = blockIdx.x * blockDim.x + threadIdx.x;
    if (gid < O_) {
        float w = fmaxf(w_sigma[gid], -88.0f);
        g_sp[gid] = log1pf(expf(w));
    }
    if (gid >= O_ * C_) return;
    int o = gid >> 7, c = gid & 127;
    int og = o >> 7, ol = o & 127;
    const float* wp = W + ((size_t)o * C_ + c) * KK;
    int dst_in = ol * 128 + c;
    #pragma unroll
    for (int tap = 0; tap < KK; ++tap) {
        float w  = wp[tap];
        size_t blk0 = (size_t)((0 * 2 + og) * KK + tap);
        size_t blk1 = (size_t)((1 * 2 + og) * KK + tap);
        g_Wp[blk0 * 16384 + dst_in] = __half_as_ushort(__float2half(w));
        g_Wp[blk1 * 16384 + dst_in] = __bfloat16_as_ushort(__float2bfloat16(w * w));
    }
}

__global__ void boxsum_kernel() {
    int i = blockIdx.x * blockDim.x + threadIdx.x;
    if (i >= B_*HW_OUT) return;
    int b = i / HW_OUT;
    int p = i - b * HW_OUT;
    int y = p / WO;
    int x = p - y * WO;
    const float* t0 = g_Tp + (size_t)b * HW_IN;
    const float* t1 = g_Tp + (size_t)(B_ + b) * HW_IN;
    float acc = 0.0f;
    #pragma unroll
    for (int dy = 0; dy < KH; ++dy)
        #pragma unroll
        for (int dx = 0; dx < KH; ++dx) {
            int off = (y + dy) * W_ + (x + dx);
            acc += t0[off] + t1[off];
        }
    g_S[i] = acc;
}

// ---------------- main mma.sync conv: k64 stages, ring-3, 2 CTA/SM ----------------
// R14 structure (proven 1464us): 256 thr, warp grid 2x4, warp tile 64x32.
// Added: B-fragment software pipeline one k16-slice ahead (+8 regs) so the
// scheduler has independent ldsm work to overlap with each MMA block.
// Buffer (32KB): A 16K | B 16K. Ring of 3 = 96KB. Both paths single-term.
// Row = one 128B line. SW128 swizzle: addr = row*128 + ((chunk ^ (row&7))<<4);
// slice ks selects chunks via addr ^ (ks<<5).
#define BUFSZ   32768u
#define OFF_BH  16384u
#define SMEM_MAIN 98304   // >= epilogue 128*132*4 = 67584

__global__ void __launch_bounds__(256, 2)
mma_conv_kernel(const float* __restrict__ bias, float* __restrict__ out) {
    extern __shared__ char smem[];
    uint32_t sb = smem_u32(smem);
    int tid = threadIdx.x;
    int lane = tid & 31, wid = tid >> 5;
    int warp_m = wid >> 2, warp_n = wid & 3;

    int ptile = blockIdx.x, b = blockIdx.y;
    int path = blockIdx.z & 1, og = blockIdx.z >> 1;

    // ---- staging setup: row = tid>>1 (0..127), half = tid&1 (64B each) ----
    int ar  = tid >> 1;
    int ah2 = tid & 1;
    int pA  = ptile * 128 + ar;
    int pcA = min(pA, HW_OUT - 1);
    int py = pcA / WO, px = pcA - py * WO;
    const unsigned short* aplane = g_Ah + (size_t)(path * B_ + b) * HW_IN * 128;
    uint32_t a_sm_base = (uint32_t)ar * 128;
    int aq = ar & 7;

    const char* wblk = (const char*)g_Wp +
        (size_t)((path * 2 + og) * KK) * 32768;

    auto stage = [&](int s, int buf) {
        int tap = s >> 1, kc = s & 1;
        int ki = tap / 5, kj = tap - ki * 5;
        uint32_t base = sb + buf * BUFSZ;
        // A: 64B half of this pixel-row's 128B k64 chunk
        const char* arow =
            (const char*)(aplane + ((size_t)((py + ki) * W_ + (px + kj))) * 128)
            + kc * 128 + ah2 * 64;
        uint32_t adst = base + a_sm_base;
        #pragma unroll
        for (int jj = 0; jj < 4; ++jj) {
            int j = 4 * ah2 + jj;
            cp16(adst + (uint32_t)((j ^ aq) << 4), arow + jj * 16);
        }
        // B: 64B half of weight row ar's 128B k64 chunk
        const char* bsrc = wblk + (size_t)tap * 32768
                         + (size_t)ar * 256 + kc * 128 + ah2 * 64;
        uint32_t bdst = base + OFF_BH + a_sm_base;
        #pragma unroll
        for (int jj = 0; jj < 4; ++jj) {
            int j = 4 * ah2 + jj;
            cp16(bdst + (uint32_t)((j ^ aq) << 4), bsrc + jj * 16);
        }
        cp_commit();
    };

    // ---- ldmatrix swizzled base offsets (slice ks XORs addr with ks<<5) ----
    int rA = warp_m * 64 + (lane & 15);
    int cA = lane >> 4;
    uint32_t offA[4];
    #pragma unroll
    for (int mi = 0; mi < 4; ++mi) {
        int row = rA + mi * 16;
        offA[mi] = (uint32_t)(row * 128 + ((cA ^ (row & 7)) << 4));
    }
    int rB = warp_n * 32 + ((lane >> 4) << 3) + (lane & 7);
    int cB = (lane >> 3) & 1;
    uint32_t offB[2];
    #pragma unroll
    for (int n2 = 0; n2 < 2; ++n2) {
        int row = rB + n2 * 16;
        offB[n2] = (uint32_t)(row * 128 + ((cB ^ (row & 7)) << 4));
    }

    float acc[4][4][4];
    #pragma unroll
    for (int mi = 0; mi < 4; ++mi)
        #pragma unroll
        for (int ni = 0; ni < 4; ++ni)
            #pragma unroll
            for (int j = 0; j < 4; ++j) acc[mi][ni][j] = 0.0f;

    stage(0, 0);
    stage(1, 1);

    for (int s = 0; s < NSTAGE; ++s) {
        int buf = s % 3;
        // 1) ensure stage(s) landed (stage s+1 stays in flight)
        if (s + 1 < NSTAGE) cp_wait<1>(); else cp_wait<0>();
        // 2) publish stage(s); confirms buffer (s+2)%3 == (s-1)%3 consumed
        __syncthreads();
        // 3) refill the freed buffer
        if (s + 2 < NSTAGE) stage(s + 2, (s + 2) % 3);

        uint32_t base = sb + buf * BUFSZ;

        // B-fragment software pipeline: preload slice 0, prefetch ks+1 before
        // each MMA block so ldsm overlaps MMA.
        uint32_t bb[2][2][4];
        #pragma unroll
        for (int n2 = 0; n2 < 2; ++n2)
            ldsm4(bb[0][n2], base + OFF_BH + offB[n2]);

        #pragma unroll
        for (int ks = 0; ks < 4; ++ks) {
            int cur = ks & 1;
            uint32_t x = (uint32_t)ks << 5;
            if (ks < 3) {
                uint32_t xn = (uint32_t)(ks + 1) << 5;
                #pragma unroll
                for (int n2 = 0; n2 < 2; ++n2)
                    ldsm4(bb[cur ^ 1][n2], base + OFF_BH + (offB[n2] ^ xn));
            }
            uint32_t ah[4][4];
            #pragma unroll
            for (int mi = 0; mi < 4; ++mi)
                ldsm4(ah[mi], base + (offA[mi] ^ x));

            if (path == 0) {
                #pragma unroll
                for (int mi = 0; mi < 4; ++mi)
                    #pragma unroll
                    for (int n2 = 0; n2 < 2; ++n2) {
                        MMAH(acc[mi][2*n2],   ah[mi], bb[cur][n2][0], bb[cur][n2][1]);
                        MMAH(acc[mi][2*n2+1], ah[mi], bb[cur][n2][2], bb[cur][n2][3]);
                    }
            } else {
                #pragma unroll
                for (int mi = 0; mi < 4; ++mi)
                    #pragma unroll
                    for (int n2 = 0; n2 < 2; ++n2) {
                        MMAB(acc[mi][2*n2],   ah[mi], bb[cur][n2][0], bb[cur][n2][1]);
                        MMAB(acc[mi][2*n2+1], ah[mi], bb[cur][n2][2], bb[cur][n2][3]);
                    }
            }
        }
    }
    __syncthreads();

    // ---- epilogue: transpose via SMEM, coalesced float4 stores ----
    float* eps = (float*)smem;                 // [n=128][m pitch 132]
    #pragma unroll
    for (int mi = 0; mi < 4; ++mi) {
        int m0 = warp_m * 64 + mi * 16 + (lane >> 2);
        #pragma unroll
        for (int ni = 0; ni < 4; ++ni) {
            int n0 = warp_n * 32 + ni * 8 + 2 * (lane & 3);
            eps[n0 * 132 + m0]           = acc[mi][ni][0];
            eps[(n0 + 1) * 132 + m0]     = acc[mi][ni][1];
            eps[n0 * 132 + m0 + 8]       = acc[mi][ni][2];
            eps[(n0 + 1) * 132 + m0 + 8] = acc[mi][ni][3];
        }
    }
    __syncthreads();

    int pix0 = ptile * 128;
    int m = lane * 4;
    bool ok = (pix0 + m) < HW_OUT;
    if (path == 0) {
        #pragma unroll 1
        for (int rr = 0; rr < 16; ++rr) {
            int r = rr * 8 + wid;
            int o = og * 128 + r;
            float4 v = *(float4*)&eps[r * 132 + m];
            float bz = bias[o];
            v.x += bz; v.y += bz; v.z += bz; v.w += bz;
            if (ok)
                *(float4*)&out[((size_t)(b * O_ + o)) * HW_OUT + pix0 + m] = v;
        }
    } else {
        float* out2 = out + (size_t)B_ * O_ * HW_OUT;
        float4 sv = make_float4(0.f, 0.f, 0.f, 0.f);
        if (ok) sv = *(float4*)&g_S[(size_t)b * HW_OUT + pix0 + m];
        #pragma unroll 1
        for (int rr = 0; rr < 16; ++rr) {
            int r = rr * 8 + wid;
            int o = og * 128 + r;
            float4 v = *(float4*)&eps[r * 132 + m];
            float sp = g_sp[o];
            v.x = (sp * sv.x + v.x) * 0.001f;
            v.y = (sp * sv.y + v.y) * 0.001f;
            v.z = (sp * sv.z + v.z) * 0.001f;
            v.w = (sp * sv.w + v.w) * 0.001f;
            if (ok)
                *(float4*)&out2[((size_t)(b * O_ + o)) * HW_OUT + pix0 + m] = v;
        }
    }
}

// ---------------------------------------------------------------------------
extern "C" void kernel_launch(void* const* d_in, const int* in_sizes, int n_in,
                              void* d_out, int out_size) {
    const float* mu_x    = (const float*)d_in[0];
    const float* sigma_x = (const float*)d_in[1];
    const float* W       = (const float*)d_in[2];
    const float* bias    = (const float*)d_in[3];
    const float* w_sigma = (const float*)d_in[4];
    float* out = (float*)d_out;

    cudaFuncSetAttribute(mma_conv_kernel,
                         cudaFuncAttributeMaxDynamicSharedMemorySize, SMEM_MAIN);

    {
        dim3 g(HW_IN / 64, B_, 2);                 // 144 x 16 x 2
        transpose_split_kernel<<<g, 256>>>(mu_x, sigma_x);
    }
    wprep_kernel<<<(O_ * C_ + 255) / 256, 256>>>(W, w_sigma);
    {
        int n = B_ * HW_OUT;
        boxsum_kernel<<<(n + 255) / 256, 256>>>();
    }
    {
        dim3 grid(NPT, B_, 4);                     // 67 x 16 x 4 = 4288 CTAs
        mma_conv_kernel<<<grid, 256, SMEM_MAIN>>>(bias, out);
    }
}

// round 17
// speedup vs baseline: 1.5618x; 1.0478x over previous
#include <cuda_runtime.h>
#include <cuda_bf16.h>
#include <cuda_fp16.h>
#include <math.h>
#include <stdint.h>

#define B_  16
#define C_  128
#define O_  256
#define H_  96
#define W_  96
#define KH  5
#define HO  92
#define WO  92
#define HW_IN  (H_*W_)        // 9216
#define HW_OUT (HO*WO)        // 8464
#define KK  25
#define NPT 67                // ceil(8464/128)
#define NSTAGE 50             // 25 taps * 2 k64-chunks

// ---------------- device scratch (no allocation allowed) ----------------
// 16-bit planes: path0 = fp16 mu, path1 = bf16 sigma  [path][b][pix][c]
__device__ __align__(128) unsigned short g_Ah[(size_t)2*B_*HW_IN*128];
// Weights: [path][og][tap][o_local(128)][c(128)]: path0 = fp16 W, path1 = bf16 W^2
__device__ __align__(128) unsigned short g_Wp[(size_t)2*2*KK*16384];
__device__ float g_Tp[2*B_*HW_IN];   // [path][b][pix]: path0 = sum mu^2, path1 = sum sigma
__device__ float g_S [B_*HW_OUT];
__device__ float g_sp[O_];

// ---------------- PTX helpers ----------------
__device__ __forceinline__ uint32_t smem_u32(const void* p){
    return (uint32_t)__cvta_generic_to_shared((void*)p);
}
__device__ __forceinline__ void cp16(uint32_t dst, const void* src){
    asm volatile("cp.async.cg.shared.global [%0], [%1], 16;\n" :: "r"(dst), "l"(src));
}
__device__ __forceinline__ void cp_commit(){ asm volatile("cp.async.commit_group;\n" ::: "memory"); }
template<int N> __device__ __forceinline__ void cp_wait(){
    asm volatile("cp.async.wait_group %0;\n" :: "n"(N) : "memory");
}
__device__ __forceinline__ void ldsm4(uint32_t* r, uint32_t addr){
    asm volatile("ldmatrix.sync.aligned.m8n8.x4.shared.b16 {%0,%1,%2,%3}, [%4];"
        : "=r"(r[0]), "=r"(r[1]), "=r"(r[2]), "=r"(r[3]) : "r"(addr));
}
// bf16 MMA (sigma path)
#define MMAB(acc, a, b0, b1)                                                       \
    asm volatile("mma.sync.aligned.m16n8k16.row.col.f32.bf16.bf16.f32 "            \
                 "{%0,%1,%2,%3},{%4,%5,%6,%7},{%8,%9},{%0,%1,%2,%3};"              \
                 : "+f"((acc)[0]), "+f"((acc)[1]), "+f"((acc)[2]), "+f"((acc)[3])  \
                 : "r"((a)[0]), "r"((a)[1]), "r"((a)[2]), "r"((a)[3]),             \
                   "r"(b0), "r"(b1))
// fp16 MMA (mu path)
#define MMAH(acc, a, b0, b1)                                                       \
    asm volatile("mma.sync.aligned.m16n8k16.row.col.f32.f16.f16.f32 "              \
                 "{%0,%1,%2,%3},{%4,%5,%6,%7},{%8,%9},{%0,%1,%2,%3};"              \
                 : "+f"((acc)[0]), "+f"((acc)[1]), "+f"((acc)[2]), "+f"((acc)[3])  \
                 : "r"((a)[0]), "r"((a)[1]), "r"((a)[2]), "r"((a)[3]),             \
                   "r"(b0), "r"(b1))

// ---------------- prep kernels ----------------
__global__ void transpose_split_kernel(const float* __restrict__ mu,
                                       const float* __restrict__ sg) {
    __shared__ float ts[C_][65];
    int pt = blockIdx.x, b = blockIdx.y, path = blockIdx.z;
    const float* src = (path ? sg : mu) + (size_t)b * C_ * HW_IN + pt * 64;
    int tid = threadIdx.x;
    for (int i = tid; i < C_ * 64; i += 256) {
        int c = i >> 6, pi = i & 63;
        ts[c][pi] = src[(size_t)c * HW_IN + pi];
    }
    __syncthreads();
    size_t obase = (size_t)(path * B_ + b) * HW_IN * 128;
    int p0 = pt * 64;
    for (int i = tid; i < 64 * C_; i += 256) {
        int pi = i >> 7, c = i & 127;
        float v = ts[c][pi];
        size_t idx = obase + (size_t)(p0 + pi) * 128 + c;
        g_Ah[idx] = path == 0 ? __half_as_ushort(__float2half(v))
                              : __bfloat16_as_ushort(__float2bfloat16(v));
    }
    // fused channel sum: path0 -> sum mu^2, path1 -> sum sigma
    if (tid < 64) {
        float acc = 0.0f;
        #pragma unroll 8
        for (int c = 0; c < C_; ++c) {
            float v = ts[c][tid];
            acc += path ? v : v * v;
        }
        g_Tp[(size_t)(path * B_ + b) * HW_IN + p0 + tid] = acc;
    }
}

__global__ void wprep_kernel(const float* __restrict__ W,
                             const float* __restrict__ w_sigma) {
    int gid = blockIdx.x * blockDim.x + threadIdx.x;
    if (gid < O_) {
        float w = fmaxf(w_sigma[gid], -88.0f);
        g_sp[gid] = log1pf(expf(w));
    }
    if (gid >= O_ * C_) return;
    int o = gid >> 7, c = gid & 127;
    int og = o >> 7, ol = o & 127;
    const float* wp = W + ((size_t)o * C_ + c) * KK;
    int dst_in = ol * 128 + c;
    #pragma unroll
    for (int tap = 0; tap < KK; ++tap) {
        float w  = wp[tap];
        size_t blk0 = (size_t)((0 * 2 + og) * KK + tap);
        size_t blk1 = (size_t)((1 * 2 + og) * KK + tap);
        g_Wp[blk0 * 16384 + dst_in] = __half_as_ushort(__float2half(w));
        g_Wp[blk1 * 16384 + dst_in] = __bfloat16_as_ushort(__float2bfloat16(w * w));
    }
}

__global__ void boxsum_kernel() {
    int i = blockIdx.x * blockDim.x + threadIdx.x;
    if (i >= B_*HW_OUT) return;
    int b = i / HW_OUT;
    int p = i - b * HW_OUT;
    int y = p / WO;
    int x = p - y * WO;
    const float* t0 = g_Tp + (size_t)b * HW_IN;
    const float* t1 = g_Tp + (size_t)(B_ + b) * HW_IN;
    float acc = 0.0f;
    #pragma unroll
    for (int dy = 0; dy < KH; ++dy)
        #pragma unroll
        for (int dx = 0; dx < KH; ++dx) {
            int off = (y + dy) * W_ + (x + dx);
            acc += t0[off] + t1[off];
        }
    g_S[i] = acc;
}

// ---------------- main mma.sync conv: k64 stages, ring-3, 2 CTA/SM ----------------
// R14 structure (proven best). Stage loop manually unrolled by the ring period
// (3) so buffer indices are compile-time constants: buffer base addresses
// constant-fold and ptxas schedules across a 3-stage window between barriers.
// Buffer (32KB): A 16K | B 16K. Ring of 3 = 96KB. Both paths single-term.
// Row = one 128B line. SW128 swizzle: addr = row*128 + ((chunk ^ (row&7))<<4);
// k16-slice ks selects chunks via addr ^ (ks<<5).
#define BUFSZ   32768u
#define OFF_BH  16384u
#define SMEM_MAIN 98304   // >= epilogue 128*132*4 = 67584

__global__ void __launch_bounds__(256, 2)
mma_conv_kernel(const float* __restrict__ bias, float* __restrict__ out) {
    extern __shared__ char smem[];
    uint32_t sb = smem_u32(smem);
    int tid = threadIdx.x;
    int lane = tid & 31, wid = tid >> 5;
    int warp_m = wid >> 2, warp_n = wid & 3;

    int ptile = blockIdx.x, b = blockIdx.y;
    int path = blockIdx.z & 1, og = blockIdx.z >> 1;

    // ---- staging setup: row = tid>>1 (0..127), half = tid&1 (64B each) ----
    int ar  = tid >> 1;
    int ah2 = tid & 1;
    int pA  = ptile * 128 + ar;
    int pcA = min(pA, HW_OUT - 1);
    int py = pcA / WO, px = pcA - py * WO;
    const unsigned short* aplane = g_Ah + (size_t)(path * B_ + b) * HW_IN * 128;
    uint32_t a_sm_base = (uint32_t)ar * 128;
    int aq = ar & 7;

    const char* wblk = (const char*)g_Wp +
        (size_t)((path * 2 + og) * KK) * 32768;

    auto stage = [&](int s, uint32_t buf_base) {
        int tap = s >> 1, kc = s & 1;
        int ki = tap / 5, kj = tap - ki * 5;
        // A: 64B half of this pixel-row's 128B k64 chunk
        const char* arow =
            (const char*)(aplane + ((size_t)((py + ki) * W_ + (px + kj))) * 128)
            + kc * 128 + ah2 * 64;
        uint32_t adst = buf_base + a_sm_base;
        #pragma unroll
        for (int jj = 0; jj < 4; ++jj) {
            int j = 4 * ah2 + jj;
            cp16(adst + (uint32_t)((j ^ aq) << 4), arow + jj * 16);
        }
        // B: 64B half of weight row ar's 128B k64 chunk
        const char* bsrc = wblk + (size_t)tap * 32768
                         + (size_t)ar * 256 + kc * 128 + ah2 * 64;
        uint32_t bdst = buf_base + OFF_BH + a_sm_base;
        #pragma unroll
        for (int jj = 0; jj < 4; ++jj) {
            int j = 4 * ah2 + jj;
            cp16(bdst + (uint32_t)((j ^ aq) << 4), bsrc + jj * 16);
        }
        cp_commit();
    };

    // ---- ldmatrix swizzled base offsets (slice ks XORs addr with ks<<5) ----
    int rA = warp_m * 64 + (lane & 15);
    int cA = lane >> 4;
    uint32_t offA[4];
    #pragma unroll
    for (int mi = 0; mi < 4; ++mi) {
        int row = rA + mi * 16;
        offA[mi] = (uint32_t)(row * 128 + ((cA ^ (row & 7)) << 4));
    }
    int rB = warp_n * 32 + ((lane >> 4) << 3) + (lane & 7);
    int cB = (lane >> 3) & 1;
    uint32_t offB[2];
    #pragma unroll
    for (int n2 = 0; n2 < 2; ++n2) {
        int row = rB + n2 * 16;
        offB[n2] = (uint32_t)(row * 128 + ((cB ^ (row & 7)) << 4));
    }

    float acc[4][4][4];
    #pragma unroll
    for (int mi = 0; mi < 4; ++mi)
        #pragma unroll
        for (int ni = 0; ni < 4; ++ni)
            #pragma unroll
            for (int j = 0; j < 4; ++j) acc[mi][ni][j] = 0.0f;

    // compute body for one stage resident in buffer with base `base`
    auto compute = [&](uint32_t base) {
        #pragma unroll
        for (int ks = 0; ks < 4; ++ks) {
            uint32_t x = (uint32_t)ks << 5;
            uint32_t ah[4][4], bh[2][4];
            #pragma unroll
            for (int mi = 0; mi < 4; ++mi)
                ldsm4(ah[mi], base + (offA[mi] ^ x));
            #pragma unroll
            for (int n2 = 0; n2 < 2; ++n2)
                ldsm4(bh[n2], base + OFF_BH + (offB[n2] ^ x));

            if (path == 0) {
                #pragma unroll
                for (int mi = 0; mi < 4; ++mi)
                    #pragma unroll
                    for (int n2 = 0; n2 < 2; ++n2) {
                        MMAH(acc[mi][2*n2],   ah[mi], bh[n2][0], bh[n2][1]);
                        MMAH(acc[mi][2*n2+1], ah[mi], bh[n2][2], bh[n2][3]);
                    }
            } else {
                #pragma unroll
                for (int mi = 0; mi < 4; ++mi)
                    #pragma unroll
                    for (int n2 = 0; n2 < 2; ++n2) {
                        MMAB(acc[mi][2*n2],   ah[mi], bh[n2][0], bh[n2][1]);
                        MMAB(acc[mi][2*n2+1], ah[mi], bh[n2][2], bh[n2][3]);
                    }
            }
        }
    };

    const uint32_t base0 = sb, base1 = sb + BUFSZ, base2 = sb + 2 * BUFSZ;

    stage(0, base0);
    stage(1, base1);

    // 48 = 3*16 full ring periods with compile-time buffer constants
    #pragma unroll 1
    for (int s = 0; s < 48; s += 3) {
        // stage s in buf0
        cp_wait<1>(); __syncthreads();
        stage(s + 2, base2);
        compute(base0);
        // stage s+1 in buf1
        cp_wait<1>(); __syncthreads();
        stage(s + 3, base0);
        compute(base1);
        // stage s+2 in buf2
        cp_wait<1>(); __syncthreads();
        if (s + 4 < NSTAGE) stage(s + 4, base1);
        compute(base2);
    }
    // remainder: s = 48 (buf0), 49 (buf1); stage(49) already issued at s+4=49
    cp_wait<1>(); __syncthreads();
    compute(base0);
    cp_wait<0>(); __syncthreads();
    compute(base1);

    __syncthreads();

    // ---- epilogue: transpose via SMEM, coalesced float4 stores ----
    float* eps = (float*)smem;                 // [n=128][m pitch 132]
    #pragma unroll
    for (int mi = 0; mi < 4; ++mi) {
        int m0 = warp_m * 64 + mi * 16 + (lane >> 2);
        #pragma unroll
        for (int ni = 0; ni < 4; ++ni) {
            int n0 = warp_n * 32 + ni * 8 + 2 * (lane & 3);
            eps[n0 * 132 + m0]           = acc[mi][ni][0];
            eps[(n0 + 1) * 132 + m0]     = acc[mi][ni][1];
            eps[n0 * 132 + m0 + 8]       = acc[mi][ni][2];
            eps[(n0 + 1) * 132 + m0 + 8] = acc[mi][ni][3];
        }
    }
    __syncthreads();

    int pix0 = ptile * 128;
    int m = lane * 4;
    bool ok = (pix0 + m) < HW_OUT;
    if (path == 0) {
        #pragma unroll 1
        for (int rr = 0; rr < 16; ++rr) {
            int r = rr * 8 + wid;
            int o = og * 128 + r;
            float4 v = *(float4*)&eps[r * 132 + m];
            float bz = bias[o];
            v.x += bz; v.y += bz; v.z += bz; v.w += bz;
            if (ok)
                *(float4*)&out[((size_t)(b * O_ + o)) * HW_OUT + pix0 + m] = v;
        }
    } else {
        float* out2 = out + (size_t)B_ * O_ * HW_OUT;
        float4 sv = make_float4(0.f, 0.f, 0.f, 0.f);
        if (ok) sv = *(float4*)&g_S[(size_t)b * HW_OUT + pix0 + m];
        #pragma unroll 1
        for (int rr = 0; rr < 16; ++rr) {
            int r = rr * 8 + wid;
            int o = og * 128 + r;
            float4 v = *(float4*)&eps[r * 132 + m];
            float sp = g_sp[o];
            v.x = (sp * sv.x + v.x) * 0.001f;
            v.y = (sp * sv.y + v.y) * 0.001f;
            v.z = (sp * sv.z + v.z) * 0.001f;
            v.w = (sp * sv.w + v.w) * 0.001f;
            if (ok)
                *(float4*)&out2[((size_t)(b * O_ + o)) * HW_OUT + pix0 + m] = v;
        }
    }
}

// ---------------------------------------------------------------------------
extern "C" void kernel_launch(void* const* d_in, const int* in_sizes, int n_in,
                              void* d_out, int out_size) {
    const float* mu_x    = (const float*)d_in[0];
    const float* sigma_x = (const float*)d_in[1];
    const float* W       = (const float*)d_in[2];
    const float* bias    = (const float*)d_in[3];
    const float* w_sigma = (const float*)d_in[4];
    float* out = (float*)d_out;

    cudaFuncSetAttribute(mma_conv_kernel,
                         cudaFuncAttributeMaxDynamicSharedMemorySize, SMEM_MAIN);

    {
        dim3 g(HW_IN / 64, B_, 2);                 // 144 x 16 x 2
        transpose_split_kernel<<<g, 256>>>(mu_x, sigma_x);
    }
    wprep_kernel<<<(O_ * C_ + 255) / 256, 256>>>(W, w_sigma);
    {
        int n = B_ * HW_OUT;
        boxsum_kernel<<<(n + 255) / 256, 256>>>();
    }
    {
        dim3 grid(NPT, B_, 4);                     // 67 x 16 x 4 = 4288 CTAs
        mma_conv_kernel<<<grid, 256, SMEM_MAIN>>>(bias, out);
    }
}